// round 16
// baseline (speedup 1.0000x reference)
#include <cuda_runtime.h>
#include <math.h>

#define N_ANCH   172032
#define MAX_OUT  200
#define NMS_TH   0.4f
#define THRF     2.9f          // fixed compaction threshold; exactness-safe (prefix argument)
#define CAP      2048
#define M        256           // NMS working set (top-M); shortfall -> exact backstop
#define MW       (M / 32)      // mask words = 8

// ---------------- static device scratch ----------------
__device__ unsigned g_ncand;             // BSS-zero; reset by tail each run
__device__ unsigned g_done;              // last-block counter (self-resetting)
__device__ unsigned long long g_ckey[CAP];
__device__ float    g_scores[N_ANCH];    // exact backstop only

// ---------------- decode helper (matches reference _decode) ----------------
__device__ __forceinline__ void decode_box(const float4& rg, const float4& an,
                                           float& y1, float& x1, float& y2, float& x2,
                                           float& ar) {
    float dx = rg.x * 0.1f, dy = rg.y * 0.1f, dw = rg.z * 0.2f, dh = rg.w * 0.2f;
    float xc = dx * an.z + an.x;
    float yc = dy * an.w + an.y;
    float w  = expf(dw) * an.z;
    float h  = expf(dh) * an.w;
    y1 = yc - 0.5f * h;  x1 = xc - 0.5f * w;
    y2 = yc + 0.5f * h;  x2 = xc + 0.5f * w;
    ar = (y2 - y1) * (x2 - x1);
}

__device__ __forceinline__ float iou_f(float ay1, float ax1, float ay2, float ax2, float aar,
                                       float by1, float bx1, float by2, float bx2, float bar) {
    float ih = fmaxf(fminf(ay2, by2) - fmaxf(ay1, by1), 0.f);
    float iw = fmaxf(fminf(ax2, bx2) - fmaxf(ax1, bx1), 0.f);
    float inter = ih * iw;
    return inter / (aar + bar - inter + 1e-12f);
}

__device__ __forceinline__ unsigned lowmask(int w, int wi, int bi) {
    return (w < wi) ? 0xFFFFFFFFu : ((w == wi) ? ((1u << bi) - 1u) : 0u);
}

// full re-decode gather (exact backstop path only)
__device__ __forceinline__ void gather_one(int t, int idx, float m,
                                           const float4* __restrict__ reg4,
                                           const float*  __restrict__ lnd,
                                           const float4* __restrict__ anch4,
                                           float* __restrict__ out) {
    float4 rg = __ldg(reg4 + idx);
    float4 an = __ldg(anch4 + idx);
    float y1, x1, y2, x2, ar;
    decode_box(rg, an, y1, x1, y2, x2, ar);
    out[4 * t + 0] = y1 * m;
    out[4 * t + 1] = x1 * m;
    out[4 * t + 2] = y2 * m;
    out[4 * t + 3] = x2 * m;
    const float* lp = lnd + 10 * idx;
    float* op = out + 4 * MAX_OUT + 10 * t;
#pragma unroll
    for (int k = 0; k < 5; k++) {
        float lx = lp[2 * k]     * 0.1f * an.z + an.x;
        float ly = lp[2 * k + 1] * 0.1f * an.w + an.y;
        op[2 * k]     = lx * m;
        op[2 * k + 1] = ly * m;
    }
}

// ======================= ONE fused kernel (last-block-done) =======================
__global__ __launch_bounds__(256) void nms_fused(const float4* __restrict__ cls4,
                                                 const float4* __restrict__ reg4,
                                                 const float*  __restrict__ lnd,
                                                 const float4* __restrict__ anch4,
                                                 int n, float* __restrict__ out) {
    __shared__ unsigned long long sk[CAP];    // 16KB keys (tail); reused by backstop
    __shared__ unsigned ssup[M * MW];         // 8KB lower-triangle suppression bits
    __shared__ float4   sb4[M];               // 4KB decoded boxes
    __shared__ float4   san[M];               // 4KB anchors
    __shared__ float    sar[M];               // 1KB areas
    __shared__ int      sidx[M];              // 1KB original indices
    __shared__ short    ssel[MAX_OUT];
    __shared__ unsigned s_sel[MW], s_new[MW], s_pref[MW];
    __shared__ int      s_nsel, s_last;
    __shared__ unsigned s_ncall;

    const int t = threadIdx.x;
    const int nv = n >> 1;

    // ---- phase 1: compact (all blocks; 1 float4 per thread) ----
    {
        int v = blockIdx.x * 256 + t;
        if (v < nv) {
            float4 c = __ldg(cls4 + v);
            if (c.y > THRF) {
                unsigned u = __float_as_uint(c.y) ^ 0x80000000u;
                unsigned pos = atomicAdd(&g_ncand, 1u);
                if (pos < CAP)
                    g_ckey[pos] = ((unsigned long long)u << 32) | (unsigned)(~(unsigned)(2 * v));
            }
            if (c.w > THRF) {
                unsigned u = __float_as_uint(c.w) ^ 0x80000000u;
                unsigned pos = atomicAdd(&g_ncand, 1u);
                if (pos < CAP)
                    g_ckey[pos] = ((unsigned long long)u << 32) | (unsigned)(~(unsigned)(2 * v + 1));
            }
        }
        if ((n & 1) && v == 0) {              // generality guard (n even here)
            float s = ((const float*)cls4)[2 * (n - 1) + 1];
            if (s > THRF) {
                unsigned u = __float_as_uint(s) ^ 0x80000000u;
                unsigned pos = atomicAdd(&g_ncand, 1u);
                if (pos < CAP)
                    g_ckey[pos] = ((unsigned long long)u << 32) | (unsigned)(~(unsigned)(n - 1));
            }
        }
    }
    __threadfence();                          // publish appends before arrival
    __syncthreads();
    if (t == 0) {
        unsigned d = atomicAdd(&g_done, 1u);
        int last = (d == gridDim.x - 1);
        if (last) atomicExch(&g_done, 0u);    // self-reset for next replay
        s_last = last;
    }
    __syncthreads();
    if (!s_last) return;                      // only the last-done block continues

    // ---- tail: single block ----
    if (t == 0) {
        s_ncall = atomicAdd(&g_ncand, 0u);    // L2-coherent read
        atomicExch(&g_ncand, 0u);             // reset for next replay
    }
    __syncthreads();
    unsigned nc_all = s_ncall;
    bool ok = (nc_all > 0u) && (nc_all <= CAP);
    unsigned nc = (nc_all < M) ? nc_all : M;
    int nsel = -1;                            // -1 => backstop required

    if (ok) {
        // load keys into smem
        unsigned ncr = (nc_all + 3u) & ~3u;
        for (int k = t; k < (int)ncr; k += 256)
            sk[k] = (k < (int)nc_all) ? g_ckey[k] : 0ULL;
        __syncthreads();

        // rank: 1 thread per candidate (no warp collectives -> no sync hazards)
        for (int base = 0; base < (int)nc_all; base += 256) {
            int c = base + t;
            if (c < (int)nc_all) {
                unsigned long long mykey = sk[c];
                int r = 0;
                int j = 0;
                for (; j + 3 < (int)ncr; j += 4) {    // 4 independent LDS -> MLP
                    r += (sk[j]     > mykey) ? 1 : 0;
                    r += (sk[j + 1] > mykey) ? 1 : 0;
                    r += (sk[j + 2] > mykey) ? 1 : 0;
                    r += (sk[j + 3] > mykey) ? 1 : 0;
                }
                for (; j < (int)ncr; j++)
                    r += (sk[j] > mykey) ? 1 : 0;
                if (r < M) {                   // ranks unique -> race-free scatter
                    int idx = (int)(~(unsigned)(mykey & 0xFFFFFFFFull));
                    sidx[r] = idx;
                    float4 rg = __ldg(reg4 + idx);
                    float4 an = __ldg(anch4 + idx);
                    float y1, x1, y2, x2, ar;
                    decode_box(rg, an, y1, x1, y2, x2, ar);
                    sb4[r] = make_float4(y1, x1, y2, x2);
                    san[r] = an;
                    sar[r] = ar;
                }
            }
        }
        __syncthreads();

        // pairs: lower triangle only (Jacobi's lowmask never reads j >= i)
        for (int k = t; k < M * MW; k += 256) {
            int i = k >> 3, w = k & 7;
            unsigned word = 0;
            if (w <= (i >> 5)) {
                float4 bi = sb4[i];
                float  ai = sar[i];
#pragma unroll 8
                for (int jj = 0; jj < 32; jj++) {
                    int j = (w << 5) + jj;
                    float4 bj = sb4[j];
                    if (iou_f(bi.x, bi.y, bi.z, bi.w, ai,
                              bj.x, bj.y, bj.z, bj.w, sar[j]) > NMS_TH)
                        word |= (1u << jj);
                }
            }
            ssup[k] = word;
        }
        if (t < MW) {
            int rem = (int)nc - t * 32;
            s_sel[t] = (rem >= 32) ? 0xFFFFFFFFu : ((rem <= 0) ? 0u : ((1u << rem) - 1u));
        }
        __syncthreads();

        // Jacobi fixed-point: sel[i] = valid[i] & !(OR_{j<i} supp[i][j] & sel[j])
        int converged = 0;
        for (int iter = 0; iter < 24; iter++) {
            int i = t;
            int wi = i >> 5, bi = i & 31;
            const uint4* r4 = (const uint4*)&ssup[i << 3];
            unsigned acc = 0;
#pragma unroll
            for (int q = 0; q < MW / 4; q++) {
                uint4 rv = r4[q];
                int w0 = q << 2;
                acc |= rv.x & s_sel[w0]     & lowmask(w0,     wi, bi);
                acc |= rv.y & s_sel[w0 + 1] & lowmask(w0 + 1, wi, bi);
                acc |= rv.z & s_sel[w0 + 2] & lowmask(w0 + 2, wi, bi);
                acc |= rv.w & s_sel[w0 + 3] & lowmask(w0 + 3, wi, bi);
            }
            int nb = (i < (int)nc) && (acc == 0u);
            unsigned word = __ballot_sync(0xFFFFFFFFu, nb);   // all 32 lanes execute
            if ((t & 31) == 0) s_new[t >> 5] = word;
            __syncthreads();
            int mydiff = 0;
            if (t < MW) {
                mydiff = (s_new[t] != s_sel[t]);
                s_sel[t] = s_new[t];
            }
            int changed = __syncthreads_or(mydiff);
            if (!changed) { converged = 1; break; }
        }

        if (converged) {
            if (t < 32) {                     // enumerate first MAX_OUT selected, in order
                unsigned w = (t < MW) ? s_sel[t] : 0u;
                int c = __popc(w);
                int inc = c;
#pragma unroll
                for (int d = 1; d < 32; d <<= 1) {
                    int v = __shfl_up_sync(0xFFFFFFFFu, inc, d);
                    if (t >= (unsigned)d) inc += v;
                }
                if (t < MW) s_pref[t] = inc - c;
                if (t == MW - 1) s_nsel = (inc > MAX_OUT) ? MAX_OUT : inc;
            }
            __syncthreads();
            {
                int i = t;
                unsigned w = s_sel[i >> 5];
                if ((w >> (i & 31)) & 1u) {
                    int order = (int)s_pref[i >> 5] + __popc(w & ((1u << (i & 31)) - 1u));
                    if (order < MAX_OUT) ssel[order] = (short)i;
                }
            }
            __syncthreads();
            nsel = s_nsel;
        }
    }

    if (nsel >= MAX_OUT) {                    // exact greedy prefix -> done (smem gather)
        if (t < MAX_OUT) {
            int r = ssel[t];
            int idx = sidx[r];
            float4 b  = sb4[r];
            float4 an = san[r];
            out[4 * t + 0] = b.x;
            out[4 * t + 1] = b.y;
            out[4 * t + 2] = b.z;
            out[4 * t + 3] = b.w;
            const float* lp = lnd + 10 * idx;
            float* op = out + 4 * MAX_OUT + 10 * t;
#pragma unroll
            for (int k = 0; k < 5; k++) {
                float lx = lp[2 * k]     * 0.1f * an.z + an.x;
                float ly = lp[2 * k + 1] * 0.1f * an.w + an.y;
                op[2 * k]     = lx;
                op[2 * k + 1] = ly;
            }
        }
        return;
    }
    __syncthreads();                          // uniform: all threads reach here together

    // ---- exact backstop (shortfall/overflow/non-convergence; ~never taken) ----
    {
        const float2* cls = (const float2*)cls4;
        float* red_s = (float*)sk;            // reuse key buffer
        int*   red_i = (int*)(sk + 128);      // offsets in ull units: 1KB each
        int*   f_idx = (int*)(sk + 256);
        int*   f_val = (int*)(sk + 384);
        for (int j = t; j < n; j += 256) {
            float s = cls[j].y;
            g_scores[j] = (s > NMS_TH) ? s : -INFINITY;
        }
        __syncthreads();
        for (int it = 0; it < MAX_OUT; it++) {
            float best = -INFINITY; int bi = 0;
            for (int j = t; j < n; j += 256) {
                float v = g_scores[j];
                if (v > best) { best = v; bi = j; }
            }
            red_s[t] = best; red_i[t] = bi;
            __syncthreads();
            for (int s = 128; s > 0; s >>= 1) {
                if (t < s) {
                    float vo = red_s[t + s]; int io = red_i[t + s];
                    if (vo > red_s[t] || (vo == red_s[t] && io < red_i[t])) {
                        red_s[t] = vo; red_i[t] = io;
                    }
                }
                __syncthreads();
            }
            int i = red_i[0];
            bool valid = (red_s[0] > -INFINITY);
            float4 rgi = __ldg(reg4 + i);
            float4 ani = __ldg(anch4 + i);
            float by1, bx1, by2, bx2, bar;
            decode_box(rgi, ani, by1, bx1, by2, bx2, bar);
            if (valid) {
                for (int j = t; j < n; j += 256) {
                    if (g_scores[j] > -INFINITY) {
                        float4 rg = __ldg(reg4 + j);
                        float4 an = __ldg(anch4 + j);
                        float y1, x1, y2, x2, ar;
                        decode_box(rg, an, y1, x1, y2, x2, ar);
                        if (iou_f(y1, x1, y2, x2, ar, by1, bx1, by2, bx2, bar) > NMS_TH)
                            g_scores[j] = -INFINITY;
                    }
                }
            }
            if (t == 0) { f_idx[it] = i; f_val[it] = valid ? 1 : 0; }
            __syncthreads();
        }
        if (t < MAX_OUT)
            gather_one(t, f_val[t] ? f_idx[t] : 0, f_val[t] ? 1.f : 0.f, reg4, lnd, anch4, out);
    }
}

// ---------------- launch: ONE kernel ----------------
extern "C" void kernel_launch(void* const* d_in, const int* in_sizes, int n_in,
                              void* d_out, int out_size) {
    const float4* cls4  = (const float4*)d_in[0];
    const float4* reg4  = (const float4*)d_in[1];
    const float*  lnd   = (const float*)d_in[2];
    const float4* anch4 = (const float4*)d_in[3];

    int n = in_sizes[0] / 2;
    if (n > N_ANCH) n = N_ANCH;
    int nv = n >> 1;
    int blocks = (nv + 255) / 256;
    if (blocks < 1) blocks = 1;

    nms_fused<<<blocks, 256>>>(cls4, reg4, lnd, anch4, n, (float*)d_out);
}

// round 17
// speedup vs baseline: 1.0587x; 1.0587x over previous
#include <cuda_runtime.h>
#include <math.h>

#define N_ANCH   172032
#define MAX_OUT  200
#define NMS_TH   0.4f
#define THRF     2.9f          // fixed compaction threshold; exactness-safe (prefix argument)
#define CAP      2048
#define M        256           // NMS working set (top-M); shortfall -> exact backstop
#define MW       (M / 32)      // mask words = 8

// ---------------- static device scratch ----------------
__device__ unsigned g_ncand;             // BSS-zero; reset by tail each run
__device__ unsigned long long g_ckey[CAP];
__device__ float    g_scores[N_ANCH];    // exact backstop only

// ---------------- decode helper (matches reference _decode) ----------------
__device__ __forceinline__ void decode_box(const float4& rg, const float4& an,
                                           float& y1, float& x1, float& y2, float& x2,
                                           float& ar) {
    float dx = rg.x * 0.1f, dy = rg.y * 0.1f, dw = rg.z * 0.2f, dh = rg.w * 0.2f;
    float xc = dx * an.z + an.x;
    float yc = dy * an.w + an.y;
    float w  = expf(dw) * an.z;
    float h  = expf(dh) * an.w;
    y1 = yc - 0.5f * h;  x1 = xc - 0.5f * w;
    y2 = yc + 0.5f * h;  x2 = xc + 0.5f * w;
    ar = (y2 - y1) * (x2 - x1);
}

__device__ __forceinline__ float iou_f(float ay1, float ax1, float ay2, float ax2, float aar,
                                       float by1, float bx1, float by2, float bx2, float bar) {
    float ih = fmaxf(fminf(ay2, by2) - fmaxf(ay1, by1), 0.f);
    float iw = fmaxf(fminf(ax2, bx2) - fmaxf(ax1, bx1), 0.f);
    float inter = ih * iw;
    return inter / (aar + bar - inter + 1e-12f);
}

__device__ __forceinline__ unsigned lowmask(int w, int wi, int bi) {
    return (w < wi) ? 0xFFFFFFFFu : ((w == wi) ? ((1u << bi) - 1u) : 0u);
}

// full re-decode gather (exact backstop path only)
__device__ __forceinline__ void gather_one(int t, int idx, float m,
                                           const float4* __restrict__ reg4,
                                           const float*  __restrict__ lnd,
                                           const float4* __restrict__ anch4,
                                           float* __restrict__ out) {
    float4 rg = __ldg(reg4 + idx);
    float4 an = __ldg(anch4 + idx);
    float y1, x1, y2, x2, ar;
    decode_box(rg, an, y1, x1, y2, x2, ar);
    out[4 * t + 0] = y1 * m;
    out[4 * t + 1] = x1 * m;
    out[4 * t + 2] = y2 * m;
    out[4 * t + 3] = x2 * m;
    const float* lp = lnd + 10 * idx;
    float* op = out + 4 * MAX_OUT + 10 * t;
#pragma unroll
    for (int k = 0; k < 5; k++) {
        float lx = lp[2 * k]     * 0.1f * an.z + an.x;
        float ly = lp[2 * k + 1] * 0.1f * an.w + an.y;
        op[2 * k]     = lx * m;
        op[2 * k + 1] = ly * m;
    }
}

// ---------------- 1) compact candidates above fixed threshold ----------------
__global__ void compact_kernel(const float4* __restrict__ cls4, int n) {
    int nv = n >> 1;                          // one float4 = two (cls0,score) pairs
    int base = blockIdx.x * blockDim.x + threadIdx.x;
    int stride = gridDim.x * blockDim.x;
    for (int v = base; v < nv; v += stride) {
        float4 c = __ldg(cls4 + v);
        if (c.y > THRF) {
            unsigned u = __float_as_uint(c.y) ^ 0x80000000u;
            unsigned pos = atomicAdd(&g_ncand, 1u);
            if (pos < CAP)
                g_ckey[pos] = ((unsigned long long)u << 32) | (unsigned)(~(unsigned)(2 * v));
        }
        if (c.w > THRF) {
            unsigned u = __float_as_uint(c.w) ^ 0x80000000u;
            unsigned pos = atomicAdd(&g_ncand, 1u);
            if (pos < CAP)
                g_ckey[pos] = ((unsigned long long)u << 32) | (unsigned)(~(unsigned)(2 * v + 1));
        }
    }
    if ((n & 1) && base == 0) {               // generality guard (n is even here)
        float s = ((const float*)cls4)[2 * (n - 1) + 1];
        if (s > THRF) {
            unsigned u = __float_as_uint(s) ^ 0x80000000u;
            unsigned pos = atomicAdd(&g_ncand, 1u);
            if (pos < CAP)
                g_ckey[pos] = ((unsigned long long)u << 32) | (unsigned)(~(unsigned)(n - 1));
        }
    }
}

// ---------------- 2) single-block tail: rank + pairs + Jacobi greedy + gather ----------------
__global__ __launch_bounds__(256) void nms_tail(const float2* __restrict__ cls,
                                                const float4* __restrict__ reg4,
                                                const float*  __restrict__ lnd,
                                                const float4* __restrict__ anch4,
                                                int n, float* __restrict__ out) {
    __shared__ unsigned long long sk[CAP];    // 16KB keys; reused by backstop
    __shared__ unsigned ssup[M * MW];         // 8KB lower-triangle suppression bits
    __shared__ float4   sb4[M];               // 4KB decoded boxes
    __shared__ float4   san[M];               // 4KB anchors
    __shared__ float    sar[M];               // 1KB areas
    __shared__ int      sidx[M];              // 1KB original indices
    __shared__ short    ssel[MAX_OUT];
    __shared__ unsigned s_sel[MW], s_new[MW], s_pref[MW];
    __shared__ int      s_nsel;
    __shared__ unsigned s_ncall;

    const int t = threadIdx.x;

    if (t == 0) { s_ncall = g_ncand; g_ncand = 0; }   // fresh launch -> L1 flushed -> coherent
    __syncthreads();
    unsigned nc_all = s_ncall;
    bool ok = (nc_all > 0u) && (nc_all <= CAP);
    unsigned nc = (nc_all < M) ? nc_all : M;
    int nsel = -1;                            // -1 => backstop required

    if (ok) {
        // load keys into smem
        unsigned ncr = (nc_all + 3u) & ~3u;
        for (int k = t; k < (int)ncr; k += 256)
            sk[k] = (k < (int)nc_all) ? g_ckey[k] : 0ULL;
        __syncthreads();

        // rank: 1 thread per candidate (no warp collectives -> no sync hazards)
        for (int base = 0; base < (int)nc_all; base += 256) {
            int c = base + t;
            if (c < (int)nc_all) {
                unsigned long long mykey = sk[c];
                int r = 0;
                int j = 0;
                for (; j + 3 < (int)ncr; j += 4) {    // 4 independent LDS -> MLP
                    r += (sk[j]     > mykey) ? 1 : 0;
                    r += (sk[j + 1] > mykey) ? 1 : 0;
                    r += (sk[j + 2] > mykey) ? 1 : 0;
                    r += (sk[j + 3] > mykey) ? 1 : 0;
                }
                for (; j < (int)ncr; j++)
                    r += (sk[j] > mykey) ? 1 : 0;
                if (r < M) {                   // ranks unique -> race-free scatter
                    int idx = (int)(~(unsigned)(mykey & 0xFFFFFFFFull));
                    sidx[r] = idx;
                    float4 rg = __ldg(reg4 + idx);
                    float4 an = __ldg(anch4 + idx);
                    float y1, x1, y2, x2, ar;
                    decode_box(rg, an, y1, x1, y2, x2, ar);
                    sb4[r] = make_float4(y1, x1, y2, x2);
                    san[r] = an;
                    sar[r] = ar;
                }
            }
        }
        __syncthreads();

        // pairs: lower triangle only (Jacobi's lowmask never reads j >= i).
        // Uninitialized smem beyond nc is harmless: rows i>=nc ignored (nb=0),
        // cols j>=nc masked by s_sel's valid-mask; NaN IoUs compare false.
        for (int k = t; k < M * MW; k += 256) {
            int i = k >> 3, w = k & 7;
            unsigned word = 0;
            if (w <= (i >> 5)) {
                float4 bi = sb4[i];
                float  ai = sar[i];
#pragma unroll 8
                for (int jj = 0; jj < 32; jj++) {
                    int j = (w << 5) + jj;
                    float4 bj = sb4[j];
                    if (iou_f(bi.x, bi.y, bi.z, bi.w, ai,
                              bj.x, bj.y, bj.z, bj.w, sar[j]) > NMS_TH)
                        word |= (1u << jj);
                }
            }
            ssup[k] = word;
        }
        if (t < MW) {
            int rem = (int)nc - t * 32;
            s_sel[t] = (rem >= 32) ? 0xFFFFFFFFu : ((rem <= 0) ? 0u : ((1u << rem) - 1u));
        }
        __syncthreads();

        // Jacobi fixed-point: sel[i] = valid[i] & !(OR_{j<i} supp[i][j] & sel[j])
        int converged = 0;
        for (int iter = 0; iter < 24; iter++) {
            int i = t;
            int wi = i >> 5, bi = i & 31;
            const uint4* r4 = (const uint4*)&ssup[i << 3];
            unsigned acc = 0;
#pragma unroll
            for (int q = 0; q < MW / 4; q++) {
                uint4 rv = r4[q];
                int w0 = q << 2;
                acc |= rv.x & s_sel[w0]     & lowmask(w0,     wi, bi);
                acc |= rv.y & s_sel[w0 + 1] & lowmask(w0 + 1, wi, bi);
                acc |= rv.z & s_sel[w0 + 2] & lowmask(w0 + 2, wi, bi);
                acc |= rv.w & s_sel[w0 + 3] & lowmask(w0 + 3, wi, bi);
            }
            int nb = (i < (int)nc) && (acc == 0u);
            unsigned word = __ballot_sync(0xFFFFFFFFu, nb);   // all 32 lanes execute
            if ((t & 31) == 0) s_new[t >> 5] = word;
            __syncthreads();
            int mydiff = 0;
            if (t < MW) {
                mydiff = (s_new[t] != s_sel[t]);
                s_sel[t] = s_new[t];
            }
            int changed = __syncthreads_or(mydiff);
            if (!changed) { converged = 1; break; }
        }

        if (converged) {
            if (t < 32) {                     // enumerate first MAX_OUT selected, in order
                unsigned w = (t < MW) ? s_sel[t] : 0u;
                int c = __popc(w);
                int inc = c;
#pragma unroll
                for (int d = 1; d < 32; d <<= 1) {
                    int v = __shfl_up_sync(0xFFFFFFFFu, inc, d);
                    if (t >= (unsigned)d) inc += v;
                }
                if (t < MW) s_pref[t] = inc - c;
                if (t == MW - 1) s_nsel = (inc > MAX_OUT) ? MAX_OUT : inc;
            }
            __syncthreads();
            {
                int i = t;
                unsigned w = s_sel[i >> 5];
                if ((w >> (i & 31)) & 1u) {
                    int order = (int)s_pref[i >> 5] + __popc(w & ((1u << (i & 31)) - 1u));
                    if (order < MAX_OUT) ssel[order] = (short)i;
                }
            }
            __syncthreads();
            nsel = s_nsel;
        }
    }

    if (nsel >= MAX_OUT) {                    // exact greedy prefix -> done (smem gather)
        if (t < MAX_OUT) {
            int r = ssel[t];
            int idx = sidx[r];
            float4 b  = sb4[r];
            float4 an = san[r];
            out[4 * t + 0] = b.x;
            out[4 * t + 1] = b.y;
            out[4 * t + 2] = b.z;
            out[4 * t + 3] = b.w;
            const float* lp = lnd + 10 * idx;
            float* op = out + 4 * MAX_OUT + 10 * t;
#pragma unroll
            for (int k = 0; k < 5; k++) {
                float lx = lp[2 * k]     * 0.1f * an.z + an.x;
                float ly = lp[2 * k + 1] * 0.1f * an.w + an.y;
                op[2 * k]     = lx;
                op[2 * k + 1] = ly;
            }
        }
        return;
    }
    __syncthreads();                          // uniform: all threads reach here together

    // ---- exact backstop (shortfall/overflow/non-convergence; ~never taken) ----
    {
        float* red_s = (float*)sk;            // reuse key buffer
        int*   red_i = (int*)(sk + 128);      // byte offsets 1KB apart (ull units)
        int*   f_idx = (int*)(sk + 256);
        int*   f_val = (int*)(sk + 384);
        for (int j = t; j < n; j += 256) {
            float s = cls[j].y;
            g_scores[j] = (s > NMS_TH) ? s : -INFINITY;
        }
        __syncthreads();
        for (int it = 0; it < MAX_OUT; it++) {
            float best = -INFINITY; int bi = 0;
            for (int j = t; j < n; j += 256) {
                float v = g_scores[j];
                if (v > best) { best = v; bi = j; }
            }
            red_s[t] = best; red_i[t] = bi;
            __syncthreads();
            for (int s = 128; s > 0; s >>= 1) {
                if (t < s) {
                    float vo = red_s[t + s]; int io = red_i[t + s];
                    if (vo > red_s[t] || (vo == red_s[t] && io < red_i[t])) {
                        red_s[t] = vo; red_i[t] = io;
                    }
                }
                __syncthreads();
            }
            int i = red_i[0];
            bool valid = (red_s[0] > -INFINITY);
            float4 rgi = __ldg(reg4 + i);
            float4 ani = __ldg(anch4 + i);
            float by1, bx1, by2, bx2, bar;
            decode_box(rgi, ani, by1, bx1, by2, bx2, bar);
            if (valid) {
                for (int j = t; j < n; j += 256) {
                    if (g_scores[j] > -INFINITY) {
                        float4 rg = __ldg(reg4 + j);
                        float4 an = __ldg(anch4 + j);
                        float y1, x1, y2, x2, ar;
                        decode_box(rg, an, y1, x1, y2, x2, ar);
                        if (iou_f(y1, x1, y2, x2, ar, by1, bx1, by2, bx2, bar) > NMS_TH)
                            g_scores[j] = -INFINITY;
                    }
                }
            }
            if (t == 0) { f_idx[it] = i; f_val[it] = valid ? 1 : 0; }
            __syncthreads();
        }
        if (t < MAX_OUT)
            gather_one(t, f_val[t] ? f_idx[t] : 0, f_val[t] ? 1.f : 0.f, reg4, lnd, anch4, out);
    }
}

// ---------------- launch: TWO plain kernels (boundary = the sync) ----------------
extern "C" void kernel_launch(void* const* d_in, const int* in_sizes, int n_in,
                              void* d_out, int out_size) {
    const float4* cls4  = (const float4*)d_in[0];
    const float4* reg4  = (const float4*)d_in[1];
    const float*  lnd   = (const float*)d_in[2];
    const float4* anch4 = (const float4*)d_in[3];

    int n = in_sizes[0] / 2;
    if (n > N_ANCH) n = N_ANCH;

    compact_kernel<<<168, 256>>>(cls4, n);
    nms_tail<<<1, 256>>>((const float2*)cls4, reg4, lnd, anch4, n, (float*)d_out);
}